// round 15
// baseline (speedup 1.0000x reference)
#include <cuda_runtime.h>
#include <cuda_bf16.h>
#include <cstdint>
#include <math.h>

typedef unsigned long long ull;

#define HD 512
#define TT 1024
#define BB 64
#define HSEQ_STRIDE (TT * HD)  /* 524288 */

// bf16-split scratch
__device__ __nv_bfloat16 g_Ahi[33554432];   // s split (drive GEMM A)
__device__ __nv_bfloat16 g_Alo[33554432];
__device__ __nv_bfloat16 g_Chi[33554432];   // hseq split (z GEMM A, written by rec)
__device__ __nv_bfloat16 g_Clo[33554432];
__device__ __nv_bfloat16 g_Bhi[262144];     // Bs split
__device__ __nv_bfloat16 g_Blo[262144];
__device__ __nv_bfloat16 g_B2hi[262144];    // Wz split
__device__ __nv_bfloat16 g_B2lo[262144];
// cross-kernel sync
__device__ int g_dcnt[512];   // drive tiles done per (batch, t-chunk), target 4
__device__ int g_prog[64];    // rec progress: [cluster][rank] -> t

// ---------------- helpers ----------
__device__ __forceinline__ float2 upk2(ull v) {
    float2 f; asm("mov.b64 {%0,%1},%2;" : "=f"(f.x), "=f"(f.y) : "l"(v)); return f;
}
__device__ __forceinline__ ull ffma2(ull a, ull b, ull c) {
    ull d; asm("fma.rn.f32x2 %0,%1,%2,%3;" : "=l"(d) : "l"(a), "l"(b), "l"(c)); return d;
}
__device__ __forceinline__ uint32_t smem_u32(const void* p) {
    uint32_t a;
    asm("{ .reg .u64 t; cvta.to.shared.u64 t, %1; cvt.u32.u64 %0, t; }" : "=r"(a) : "l"(p));
    return a;
}
__device__ __forceinline__ void mbar_init(uint32_t mb, uint32_t cnt) {
    asm volatile("mbarrier.init.shared.b64 [%0], %1;" :: "r"(mb), "r"(cnt) : "memory");
}
__device__ __forceinline__ void mbar_expect_tx(uint32_t mb, uint32_t bytes) {
    asm volatile("mbarrier.arrive.expect_tx.shared.b64 _, [%0], %1;" :: "r"(mb), "r"(bytes) : "memory");
}
__device__ __forceinline__ void mbar_wait(uint32_t mb, uint32_t parity) {
    uint32_t done;
    asm volatile(
        "{\n\t.reg .pred p;\n\t"
        "mbarrier.try_wait.parity.acquire.cta.shared::cta.b64 p, [%1], %2;\n\t"
        "selp.b32 %0, 1, 0, p;\n\t}"
        : "=r"(done) : "r"(mb), "r"(parity) : "memory");
    if (!done) {
        asm volatile(
            "{\n\t.reg .pred P1;\n\t"
            "WL_%=:\n\t"
            "mbarrier.try_wait.parity.acquire.cta.shared::cta.b64 P1, [%0], %1, 0x989680;\n\t"
            "@P1 bra.uni WD_%=;\n\t"
            "bra.uni WL_%=;\n\t"
            "WD_%=:\n\t}"
            :: "r"(mb), "r"(parity) : "memory");
    }
}
__device__ __forceinline__ int ld_acq(const int* p) {
    int v; asm volatile("ld.acquire.gpu.u32 %0, [%1];" : "=r"(v) : "l"(p) : "memory");
    return v;
}

// ---------------------------------------------------------------------------
__global__ void init_sync() {
    for (int i = threadIdx.x; i < 512; i += blockDim.x) g_dcnt[i] = 0;
    if (threadIdx.x < 64) g_prog[threadIdx.x] = 0;
}

// ---------------------------------------------------------------------------
// cvt_split: X fp32 -> (hi, lo) bf16 arrays
// ---------------------------------------------------------------------------
__global__ void cvt_split(const float4* __restrict__ X, ull* __restrict__ hi,
                          ull* __restrict__ lo, int n4)
{
    const int stride = gridDim.x * blockDim.x;
    for (int i = blockIdx.x * blockDim.x + threadIdx.x; i < n4; i += stride) {
        float4 v = X[i];
        __nv_bfloat162 h01 = __floats2bfloat162_rn(v.x, v.y);
        __nv_bfloat162 h23 = __floats2bfloat162_rn(v.z, v.w);
        __nv_bfloat162 l01 = __floats2bfloat162_rn(v.x - __low2float(h01),
                                                   v.y - __high2float(h01));
        __nv_bfloat162 l23 = __floats2bfloat162_rn(v.z - __low2float(h23),
                                                   v.w - __high2float(h23));
        ull hv, lv;
        asm("mov.b64 %0, {%1,%2};" : "=l"(hv)
            : "r"(*(uint32_t*)&h01), "r"(*(uint32_t*)&h23));
        asm("mov.b64 %0, {%1,%2};" : "=l"(lv)
            : "r"(*(uint32_t*)&l01), "r"(*(uint32_t*)&l23));
        hi[i] = hv;
        lo[i] = lv;
    }
}

// ---------------------------------------------------------------------------
// bf16-split NT GEMM on mma.sync. T-major tile map: by -> (tc, b).
// dcnt: producer signal per (b, tc). prog: consumer gate on rec progress.
// ---------------------------------------------------------------------------
#define LDM4(r, adr) \
    asm volatile("ldmatrix.sync.aligned.m8n8.x4.shared.b16 {%0,%1,%2,%3}, [%4];" \
                 : "=r"((r)[0]), "=r"((r)[1]), "=r"((r)[2]), "=r"((r)[3]) : "r"(adr))

#define MMA16816(acc, a, b0v, b1v) \
    asm volatile("mma.sync.aligned.m16n8k16.row.col.f32.bf16.bf16.f32 " \
                 "{%0,%1,%2,%3}, {%4,%5,%6,%7}, {%8,%9}, {%0,%1,%2,%3};" \
                 : "+f"((acc)[0]), "+f"((acc)[1]), "+f"((acc)[2]), "+f"((acc)[3]) \
                 : "r"((a)[0]), "r"((a)[1]), "r"((a)[2]), "r"((a)[3]), \
                   "r"(b0v), "r"(b1v))

__device__ __forceinline__ uint32_t swz(uint32_t off) {
    return off ^ ((off >> 3) & 0x70);
}

__global__ __launch_bounds__(256, 1) void gemm_mma(
    const __nv_bfloat16* __restrict__ Ahi, const __nv_bfloat16* __restrict__ Alo,
    const __nv_bfloat16* __restrict__ Bhi, const __nv_bfloat16* __restrict__ Blo,
    float* __restrict__ C, const float* __restrict__ bias,
    const float* __restrict__ addsrc, int* dcnt, const int* prog)
{
    extern __shared__ char dsm_raw[];
    const int tid = threadIdx.x;
    const int wid = tid >> 5;
    const int lid = tid & 31;
    const int my = blockIdx.y;
    const int tcz = my >> 6;          // t-chunk 0..7
    const int bz  = my & 63;          // batch
    const int m0 = bz * 1024 + tcz * 128;
    const int n0 = blockIdx.x * 128;

    // gate on rec progress (z GEMM only)
    if (prog) {
        if (tid == 0) {
            const int gcl = bz >> 3;
            const int need = tcz * 128 + 127;
            const int* pp = prog + gcl * 8;
            for (int r = 0; r < 8; r++)
                while (ld_acq(pp + r) < need) __nanosleep(256);
        }
        __syncthreads();
    }

    uint32_t sb0 = smem_u32(dsm_raw);
    const uint32_t sbase = (sb0 + 1023u) & ~1023u;

    const int wm = (wid & 3) * 32;
    const int wn = (wid >> 2) * 64;

    float acc[2][8][4];
#pragma unroll
    for (int mt = 0; mt < 2; mt++)
#pragma unroll
        for (int nt = 0; nt < 8; nt++)
#pragma unroll
            for (int j = 0; j < 4; j++) acc[mt][nt][j] = 0.0f;

    const int rid = tid >> 1;
    const int s0 = (tid & 1) * 4;
    const __nv_bfloat16* srcA_hi = Ahi + (size_t)(m0 + rid) * HD;
    const __nv_bfloat16* srcA_lo = Alo + (size_t)(m0 + rid) * HD;
    const __nv_bfloat16* srcB_hi = Bhi + (size_t)(n0 + rid) * HD;
    const __nv_bfloat16* srcB_lo = Blo + (size_t)(n0 + rid) * HD;

    auto stage = [&](int c, int bsel) {
        const int kb = c * 64;
        const uint32_t tb = sbase + (uint32_t)bsel * 65536u;
#pragma unroll
        for (int j = 0; j < 4; j++) {
            const int seg = s0 + j;
            const uint32_t sw = swz((uint32_t)(rid * 128 + seg * 16));
            const size_t so = (size_t)(kb + seg * 8);
            asm volatile("cp.async.cg.shared.global [%0], [%1], 16;"
                         :: "r"(tb + sw), "l"(srcA_hi + so) : "memory");
            asm volatile("cp.async.cg.shared.global [%0], [%1], 16;"
                         :: "r"(tb + 16384u + sw), "l"(srcA_lo + so) : "memory");
            asm volatile("cp.async.cg.shared.global [%0], [%1], 16;"
                         :: "r"(tb + 32768u + sw), "l"(srcB_hi + so) : "memory");
            asm volatile("cp.async.cg.shared.global [%0], [%1], 16;"
                         :: "r"(tb + 49152u + sw), "l"(srcB_lo + so) : "memory");
        }
    };

    const uint32_t a_row_off0 = (uint32_t)(wm + (lid & 15)) * 128u;
    const uint32_t a_k16 = (uint32_t)(lid >> 4) * 16u;
    const uint32_t b_row_off = (uint32_t)(wn + (lid & 7) + ((lid >> 4) << 3)) * 128u;
    const uint32_t b_k16 = (uint32_t)((lid >> 3) & 1) * 16u;

    stage(0, 0);
    asm volatile("cp.async.commit_group;" ::: "memory");
    stage(1, 1);
    asm volatile("cp.async.commit_group;" ::: "memory");

    for (int c = 0; c < 8; c++) {
        asm volatile("cp.async.wait_group 1;" ::: "memory");
        __syncthreads();

        const uint32_t tb = sbase + (uint32_t)(c & 1) * 65536u;
#pragma unroll
        for (int ks = 0; ks < 4; ks++) {
            const uint32_t ka = (uint32_t)(ks * 32) + a_k16;
            const uint32_t kbcol = (uint32_t)(ks * 32) + b_k16;

            uint32_t fah0[4], fah1[4], fal0[4], fal1[4];
            LDM4(fah0, tb + swz(a_row_off0 + ka));
            LDM4(fah1, tb + swz(a_row_off0 + 2048u + ka));
            LDM4(fal0, tb + 16384u + swz(a_row_off0 + ka));
            LDM4(fal1, tb + 16384u + swz(a_row_off0 + 2048u + ka));

            uint32_t bh[4][4], bl[4][4];
#pragma unroll
            for (int nt16 = 0; nt16 < 4; nt16++) {
                const uint32_t bo = swz(b_row_off + (uint32_t)nt16 * 2048u + kbcol);
                LDM4(bh[nt16], tb + 32768u + bo);
                LDM4(bl[nt16], tb + 49152u + bo);
            }

#pragma unroll
            for (int nt16 = 0; nt16 < 4; nt16++) {
                MMA16816(acc[0][2 * nt16],     fah0, bh[nt16][0], bh[nt16][1]);
                MMA16816(acc[0][2 * nt16 + 1], fah0, bh[nt16][2], bh[nt16][3]);
                MMA16816(acc[1][2 * nt16],     fah1, bh[nt16][0], bh[nt16][1]);
                MMA16816(acc[1][2 * nt16 + 1], fah1, bh[nt16][2], bh[nt16][3]);
                MMA16816(acc[0][2 * nt16],     fah0, bl[nt16][0], bl[nt16][1]);
                MMA16816(acc[0][2 * nt16 + 1], fah0, bl[nt16][2], bl[nt16][3]);
                MMA16816(acc[1][2 * nt16],     fah1, bl[nt16][0], bl[nt16][1]);
                MMA16816(acc[1][2 * nt16 + 1], fah1, bl[nt16][2], bl[nt16][3]);
                MMA16816(acc[0][2 * nt16],     fal0, bh[nt16][0], bh[nt16][1]);
                MMA16816(acc[0][2 * nt16 + 1], fal0, bh[nt16][2], bh[nt16][3]);
                MMA16816(acc[1][2 * nt16],     fal1, bh[nt16][0], bh[nt16][1]);
                MMA16816(acc[1][2 * nt16 + 1], fal1, bh[nt16][2], bh[nt16][3]);
            }
        }
        __syncthreads();
        if (c + 2 < 8) stage(c + 2, c & 1);
        asm volatile("cp.async.commit_group;" ::: "memory");
    }

    const int r0 = lid >> 2, cp2 = (lid & 3) * 2;
#pragma unroll
    for (int mt = 0; mt < 2; mt++) {
        const int m = m0 + wm + mt * 16 + r0;
#pragma unroll
        for (int nt = 0; nt < 8; nt++) {
            const int n = n0 + wn + nt * 8 + cp2;
            float bx = 0.0f, by = 0.0f;
            if (bias) { float2 bb = *(const float2*)&bias[n]; bx = bb.x; by = bb.y; }
            float2 v0 = make_float2(acc[mt][nt][0] + bx, acc[mt][nt][1] + by);
            float2 v1 = make_float2(acc[mt][nt][2] + bx, acc[mt][nt][3] + by);
            if (addsrc) {
                float2 a0 = *(const float2*)&addsrc[(size_t)m * HD + n];
                float2 a1 = *(const float2*)&addsrc[(size_t)(m + 8) * HD + n];
                v0.x += a0.x; v0.y += a0.y;
                v1.x += a1.x; v1.y += a1.y;
            }
            *(float2*)&C[(size_t)m * HD + n] = v0;
            *(float2*)&C[(size_t)(m + 8) * HD + n] = v1;
        }
    }

    if (dcnt) {
        __syncthreads();
        if (tid == 0) { __threadfence(); atomicAdd(dcnt + bz * 8 + tcz, 1); }
    }
}

// ---------------------------------------------------------------------------
// Recurrence v9: 8 clusters x 8 CTAs, FOUR interleaved groups of 2 batches.
// While one group's cp.async.bulk exchange is in flight, three others
// compute. W (64 cols x 512 k) register-resident, shared by all groups.
// Fine-grained drive gating per (batch, chunk). Progress published /16 steps.
// ---------------------------------------------------------------------------
__global__ __launch_bounds__(256, 1) __cluster_dims__(8, 1, 1)
void rnn_rec(const float* __restrict__ h0, const float* __restrict__ drive,
             const float* __restrict__ W, float* __restrict__ hseq,
             __nv_bfloat16* __restrict__ hhi, __nv_bfloat16* __restrict__ hlo,
             int* __restrict__ dcnt, int* __restrict__ prog)
{
    __shared__ __align__(128) float buf[4][2][1024];  // [grp][par][rank*128+b*64+c]
    __shared__ __align__(128) float stg[4][2][128];   // [grp][par][b*64+c]
    __shared__ float red[4][1024];                    // [grp][ks*128+cp*4+j]
    __shared__ __align__(8) ull mbars[8];             // [grp*2+par]

    const int tid = threadIdx.x;
    uint32_t rank;
    asm("mov.u32 %0, %%cluster_ctarank;" : "=r"(rank));
    const int g   = blockIdx.x >> 3;
    const int b0g = g * 8;
    const int c0g = (int)rank * 64;

    const int ks = tid >> 5, cp = tid & 31;
    const int kbeg = ks * 64;

    // ---- W slab into registers (f32x2 k-pairs, 2 cols x 64 k per thread)
    ull Wp[64];
    {
        const int col0 = c0g + 2 * cp;
#pragma unroll
        for (int c = 0; c < 2; c++) {
            const ull* wr = (const ull*)(W + (size_t)(col0 + c) * HD + kbeg);
#pragma unroll
            for (int kk = 0; kk < 32; kk += 2) {
                ulonglong2 v = *(const ulonglong2*)(wr + kk);
                Wp[c * 32 + kk]     = v.x;
                Wp[c * 32 + kk + 1] = v.y;
            }
        }
    }

    // ---- prime buf[gi][0]: [rank*128 + b*64 + c] = h0[b0g+2gi+b][rank64..]
    for (int i = tid; i < 1024; i += 256) {
        int r = i >> 7, b = (i >> 6) & 1, c = i & 63;
        size_t base = (size_t)(b0g + b) * HD + r * 64 + c;
#pragma unroll
        for (int gi = 0; gi < 4; gi++)
            buf[gi][0][i] = h0[base + (size_t)(2 * gi) * HD];
    }
    // ---- t=0 outputs (8 batches x this CTA's 64 cols)
    for (int i = tid; i < 512; i += 256) {
        int b = i >> 6, c = i & 63;
        float v = h0[(size_t)(b0g + b) * HD + (c0g + c)];
        size_t off = (size_t)(b0g + b) * HSEQ_STRIDE + (c0g + c);
        hseq[off] = v;
        __nv_bfloat16 vh = __float2bfloat16(v);
        hhi[off] = vh;
        hlo[off] = __float2bfloat16(v - __bfloat162float(vh));
    }

    const uint32_t buf_u  = smem_u32(buf);
    const uint32_t stg_u  = smem_u32(stg);
    const uint32_t mbar_u = smem_u32(mbars);

    if (tid == 0)
#pragma unroll
        for (int i = 0; i < 8; i++) mbar_init(mbar_u + 8u * i, 1);
    __syncthreads();
    asm volatile("barrier.cluster.arrive.aligned;\n\tbarrier.cluster.wait.aligned;" ::: "memory");

    // issuer (tid<8, peer = tid): mapa the two bases once; derive by offsets
    uint32_t bufPeer = 0, mbPeer = 0;
    if (tid < 8) {
        asm volatile("mapa.shared::cluster.u32 %0, %1, %2;" : "=r"(bufPeer) : "r"(buf_u), "r"(tid));
        asm volatile("mapa.shared::cluster.u32 %0, %1, %2;" : "=r"(mbPeer) : "r"(mbar_u), "r"(tid));
    }

    // combine decomposition (tid<128): one (col,b) per thread
    const int col_l = tid >> 1, bb = tid & 1;
    const int cg = c0g + col_l;
    const size_t off0 = (size_t)(b0g + bb) * HSEQ_STRIDE + cg;   // group 0 base
    const int stg_idx  = bb * 64 + col_l;
    const int hold_idx = (int)rank * 128 + stg_idx;

    int* progP = prog + g * 8 + (int)rank;

    int ph[8];
#pragma unroll
    for (int i = 0; i < 8; i++) ph[i] = 0;

    for (int t = 1; t < TT; t++) {
        const int pr = (t - 1) & 1, pw = t & 1;

        // fine-grained drive gate (once per 128 steps; tid<8 spins one batch each)
        if (((t - 1) & 127) == 0) {
            if (tid < 8) {
                const int* dc = dcnt + (b0g + tid) * 8 + ((t - 1) >> 7);
                while (ld_acq(dc) < 4) __nanosleep(256);
            }
            __syncthreads();
        }

        // all of step t-2's bulk reads done (4 commits at t-1 may pend)
        if (tid < 8)
            asm volatile("cp.async.bulk.wait_group.read 4;" ::: "memory");

        // prefetch all 4 groups' drive values
        float xg[4];
        if (tid < 128) {
#pragma unroll
            for (int gi = 0; gi < 4; gi++)
                xg[gi] = drive[off0 + (size_t)(2 * gi) * HSEQ_STRIDE + (size_t)(t - 1) * HD];
        }

#pragma unroll
        for (int gi = 0; gi < 4; gi++) {
            if (t >= 2) { mbar_wait(mbar_u + (uint32_t)(gi * 2 + pr) * 8, ph[gi * 2 + pr]); ph[gi * 2 + pr] ^= 1; }
            if (tid == 0 && t < TT - 1) mbar_expect_tx(mbar_u + (uint32_t)(gi * 2 + pw) * 8, 4096);

            const float* bufc = buf[gi][pr];
            float hold = (tid < 128) ? bufc[hold_idx] : 0.0f;

            ull a00 = 0, a01 = 0, a10 = 0, a11 = 0;
            const float* hp = bufc + ks * 128;
#pragma unroll
            for (int i = 0; i < 16; i++) {
                ulonglong2 p0 = *(const ulonglong2*)(hp + 4 * i);
                ulonglong2 p1 = *(const ulonglong2*)(hp + 64 + 4 * i);
                ull w0 = Wp[2 * i], w1 = Wp[2 * i + 1];
                ull w2 = Wp[32 + 2 * i], w3 = Wp[32 + 2 * i + 1];
                a00 = ffma2(w0, p0.x, a00); a00 = ffma2(w1, p0.y, a00);
                a01 = ffma2(w0, p1.x, a01); a01 = ffma2(w1, p1.y, a01);
                a10 = ffma2(w2, p0.x, a10); a10 = ffma2(w3, p0.y, a10);
                a11 = ffma2(w2, p1.x, a11); a11 = ffma2(w3, p1.y, a11);
            }
            float2 s00 = upk2(a00), s01 = upk2(a01), s10 = upk2(a10), s11 = upk2(a11);
            *(float4*)&red[gi][(ks * 32 + cp) * 4] =
                make_float4(s00.x + s00.y, s01.x + s01.y, s10.x + s10.y, s11.x + s11.y);
            __syncthreads();

            if (tid < 128) {
                float s = 0.0f;
#pragma unroll
                for (int r = 0; r < 8; r++) s += red[gi][r * 128 + tid];
                float hn = 0.9f * hold + 0.1f * tanhf(s + xg[gi]);
                size_t off = off0 + (size_t)(2 * gi) * HSEQ_STRIDE + (size_t)t * HD;
                hseq[off] = hn;
                __nv_bfloat16 hb = __float2bfloat16(hn);
                hhi[off] = hb;
                hlo[off] = __float2bfloat16(hn - __bfloat162float(hb));
                stg[gi][pw][stg_idx] = hn;
            }
            __syncthreads();

            if (tid < 8 && t < TT - 1) {
                asm volatile("fence.proxy.async.shared::cta;" ::: "memory");
                uint32_t src = stg_u + (uint32_t)(gi * 2 + pw) * 512u;
                uint32_t dst = bufPeer + (uint32_t)(gi * 2 + pw) * 4096u + rank * 512u;
                uint32_t mbR = mbPeer + (uint32_t)(gi * 2 + pw) * 8u;
                asm volatile(
                    "cp.async.bulk.shared::cluster.shared::cta.mbarrier::complete_tx::bytes "
                    "[%0], [%1], %2, [%3];"
                    :: "r"(dst), "r"(src), "r"(512), "r"(mbR) : "memory");
                asm volatile("cp.async.bulk.commit_group;" ::: "memory");
            }
        }

        // publish progress every 16 steps (single gpu fence; covers all groups)
        if ((t & 15) == 15 && tid == 0) {
            __threadfence();
            asm volatile("st.release.gpu.u32 [%0], %1;" :: "l"(progP), "r"(t) : "memory");
        }
    }

    if (tid < 8) asm volatile("cp.async.bulk.wait_group.read 0;" ::: "memory");
    asm volatile("barrier.cluster.arrive.aligned;\n\tbarrier.cluster.wait.aligned;" ::: "memory");
}

// ---------------------------------------------------------------------------
extern "C" void kernel_launch(void* const* d_in, const int* in_sizes, int n_in,
                              void* d_out, int out_size)
{
    const float* h0 = (const float*)d_in[0];
    const float* s  = (const float*)d_in[1];
    const float* u  = (const float*)d_in[2];
    const float* W  = (const float*)d_in[3];
    const float* b  = (const float*)d_in[4];
    const float* Bs = (const float*)d_in[5];
    // d_in[6] = Bu (identity by construction)
    const float* Wz = (const float*)d_in[7];
    const float* bz = (const float*)d_in[8];

    float* hseq = (float*)d_out;                         // [B,T,H]
    float* zseq = (float*)d_out + (size_t)BB * TT * HD;  // [B,T,Z]
    float* drive = zseq;  // scratch; overwritten progressively by z GEMM (gated)

    void *pAhi, *pAlo, *pChi, *pClo, *pBhi, *pBlo, *pB2hi, *pB2lo, *pDc, *pPg;
    cudaGetSymbolAddress(&pAhi, g_Ahi);
    cudaGetSymbolAddress(&pAlo, g_Alo);
    cudaGetSymbolAddress(&pChi, g_Chi);
    cudaGetSymbolAddress(&pClo, g_Clo);
    cudaGetSymbolAddress(&pBhi, g_Bhi);
    cudaGetSymbolAddress(&pBlo, g_Blo);
    cudaGetSymbolAddress(&pB2hi, g_B2hi);
    cudaGetSymbolAddress(&pB2lo, g_B2lo);
    cudaGetSymbolAddress(&pDc, g_dcnt);
    cudaGetSymbolAddress(&pPg, g_prog);

    const int GEMM_SMEM = 2 * 65536 + 1024;
    cudaFuncSetAttribute(gemm_mma, cudaFuncAttributeMaxDynamicSharedMemorySize, GEMM_SMEM);

    // streams/events created ONCE on the first (non-captured) call; reused.
    static cudaStream_t s1 = nullptr, s2 = nullptr;
    static cudaEvent_t ev0 = nullptr, evF = nullptr, ev1 = nullptr, ev2 = nullptr;
    if (!s1) {
        cudaStreamCreateWithFlags(&s1, cudaStreamNonBlocking);
        cudaStreamCreateWithFlags(&s2, cudaStreamNonBlocking);
        cudaEventCreateWithFlags(&ev0, cudaEventDisableTiming);
        cudaEventCreateWithFlags(&evF, cudaEventDisableTiming);
        cudaEventCreateWithFlags(&ev1, cudaEventDisableTiming);
        cudaEventCreateWithFlags(&ev2, cudaEventDisableTiming);
    }

    dim3 blk(256);
    dim3 grd(4, 512);

    // --- prologue on capture stream ---
    init_sync<<<1, 256>>>();
    cudaEventRecord(ev0, 0);                 // rec only needs zeroed sync vars
    cvt_split<<<2048, 256>>>((const float4*)s, (ull*)pAhi, (ull*)pAlo, 8388608);
    cvt_split<<<256, 256>>>((const float4*)Bs, (ull*)pBhi, (ull*)pBlo, 65536);
    cvt_split<<<256, 256>>>((const float4*)Wz, (ull*)pB2hi, (ull*)pB2lo, 65536);
    cudaEventRecord(evF, 0);

    // --- branch 1: recurrence (starts early; gated on drive progress) ---
    cudaStreamWaitEvent(s1, ev0, 0);
    rnn_rec<<<64, 256, 0, s1>>>(h0, drive, W, hseq,
                                (__nv_bfloat16*)pChi, (__nv_bfloat16*)pClo,
                                (int*)pDc, (int*)pPg);
    cudaEventRecord(ev1, s1);

    // --- branch 2: drive GEMM (producer) then z GEMM (gated on rec) ---
    cudaStreamWaitEvent(s2, evF, 0);
    gemm_mma<<<grd, blk, GEMM_SMEM, s2>>>(
        (const __nv_bfloat16*)pAhi, (const __nv_bfloat16*)pAlo,
        (const __nv_bfloat16*)pBhi, (const __nv_bfloat16*)pBlo,
        drive, b, u, (int*)pDc, nullptr);
    gemm_mma<<<grd, blk, GEMM_SMEM, s2>>>(
        (const __nv_bfloat16*)pChi, (const __nv_bfloat16*)pClo,
        (const __nv_bfloat16*)pB2hi, (const __nv_bfloat16*)pB2lo,
        zseq, bz, nullptr, nullptr, (const int*)pPg);
    cudaEventRecord(ev2, s2);

    // --- join ---
    cudaStreamWaitEvent(0, ev1, 0);
    cudaStreamWaitEvent(0, ev2, 0);
}

// round 16
// speedup vs baseline: 1.1764x; 1.1764x over previous
#include <cuda_runtime.h>
#include <cuda_bf16.h>
#include <cstdint>
#include <math.h>

typedef unsigned long long ull;

#define HD 512
#define TT 1024
#define BB 64
#define HSEQ_STRIDE (TT * HD)  /* 524288 */

// bf16-split scratch
__device__ __nv_bfloat16 g_Ahi[33554432];   // s split (drive GEMM A)
__device__ __nv_bfloat16 g_Alo[33554432];
__device__ __nv_bfloat16 g_Chi[33554432];   // hseq split (z GEMM A, written by rec)
__device__ __nv_bfloat16 g_Clo[33554432];
__device__ __nv_bfloat16 g_Bhi[262144];     // Bs split
__device__ __nv_bfloat16 g_Blo[262144];
__device__ __nv_bfloat16 g_B2hi[262144];    // Wz split
__device__ __nv_bfloat16 g_B2lo[262144];
// cross-kernel sync
__device__ int g_dcnt[512];   // drive tiles done per (batch, t-chunk), target 4
__device__ int g_prog[64];    // rec progress: [cluster][rank] -> t

// ---------------- helpers ----------
__device__ __forceinline__ float2 upk2(ull v) {
    float2 f; asm("mov.b64 {%0,%1},%2;" : "=f"(f.x), "=f"(f.y) : "l"(v)); return f;
}
__device__ __forceinline__ ull ffma2(ull a, ull b, ull c) {
    ull d; asm("fma.rn.f32x2 %0,%1,%2,%3;" : "=l"(d) : "l"(a), "l"(b), "l"(c)); return d;
}
__device__ __forceinline__ uint32_t smem_u32(const void* p) {
    uint32_t a;
    asm("{ .reg .u64 t; cvta.to.shared.u64 t, %1; cvt.u32.u64 %0, t; }" : "=r"(a) : "l"(p));
    return a;
}
__device__ __forceinline__ void mbar_init(uint32_t mb, uint32_t cnt) {
    asm volatile("mbarrier.init.shared.b64 [%0], %1;" :: "r"(mb), "r"(cnt) : "memory");
}
__device__ __forceinline__ void mbar_expect_tx(uint32_t mb, uint32_t bytes) {
    asm volatile("mbarrier.arrive.expect_tx.shared.b64 _, [%0], %1;" :: "r"(mb), "r"(bytes) : "memory");
}
__device__ __forceinline__ void mbar_wait(uint32_t mb, uint32_t parity) {
    uint32_t done;
    asm volatile(
        "{\n\t.reg .pred p;\n\t"
        "mbarrier.try_wait.parity.acquire.cta.shared::cta.b64 p, [%1], %2;\n\t"
        "selp.b32 %0, 1, 0, p;\n\t}"
        : "=r"(done) : "r"(mb), "r"(parity) : "memory");
    if (!done) {
        asm volatile(
            "{\n\t.reg .pred P1;\n\t"
            "WL_%=:\n\t"
            "mbarrier.try_wait.parity.acquire.cta.shared::cta.b64 P1, [%0], %1, 0x989680;\n\t"
            "@P1 bra.uni WD_%=;\n\t"
            "bra.uni WL_%=;\n\t"
            "WD_%=:\n\t}"
            :: "r"(mb), "r"(parity) : "memory");
    }
}
__device__ __forceinline__ int ld_acq(const int* p) {
    int v; asm volatile("ld.acquire.gpu.u32 %0, [%1];" : "=r"(v) : "l"(p) : "memory");
    return v;
}

// ---------------------------------------------------------------------------
__global__ void init_sync() {
    for (int i = threadIdx.x; i < 512; i += blockDim.x) g_dcnt[i] = 0;
    if (threadIdx.x < 64) g_prog[threadIdx.x] = 0;
}

// ---------------------------------------------------------------------------
// cvt_split: X fp32 -> (hi, lo) bf16 arrays
// ---------------------------------------------------------------------------
__global__ void cvt_split(const float4* __restrict__ X, ull* __restrict__ hi,
                          ull* __restrict__ lo, int n4)
{
    const int stride = gridDim.x * blockDim.x;
    for (int i = blockIdx.x * blockDim.x + threadIdx.x; i < n4; i += stride) {
        float4 v = X[i];
        __nv_bfloat162 h01 = __floats2bfloat162_rn(v.x, v.y);
        __nv_bfloat162 h23 = __floats2bfloat162_rn(v.z, v.w);
        __nv_bfloat162 l01 = __floats2bfloat162_rn(v.x - __low2float(h01),
                                                   v.y - __high2float(h01));
        __nv_bfloat162 l23 = __floats2bfloat162_rn(v.z - __low2float(h23),
                                                   v.w - __high2float(h23));
        ull hv, lv;
        asm("mov.b64 %0, {%1,%2};" : "=l"(hv)
            : "r"(*(uint32_t*)&h01), "r"(*(uint32_t*)&h23));
        asm("mov.b64 %0, {%1,%2};" : "=l"(lv)
            : "r"(*(uint32_t*)&l01), "r"(*(uint32_t*)&l23));
        hi[i] = hv;
        lo[i] = lv;
    }
}

// ---------------------------------------------------------------------------
// bf16-split NT GEMM on mma.sync. T-major tile map: by -> (tc, b).
// dcnt: producer signal per (b, tc). prog: consumer gate on rec progress.
// ---------------------------------------------------------------------------
#define LDM4(r, adr) \
    asm volatile("ldmatrix.sync.aligned.m8n8.x4.shared.b16 {%0,%1,%2,%3}, [%4];" \
                 : "=r"((r)[0]), "=r"((r)[1]), "=r"((r)[2]), "=r"((r)[3]) : "r"(adr))

#define MMA16816(acc, a, b0v, b1v) \
    asm volatile("mma.sync.aligned.m16n8k16.row.col.f32.bf16.bf16.f32 " \
                 "{%0,%1,%2,%3}, {%4,%5,%6,%7}, {%8,%9}, {%0,%1,%2,%3};" \
                 : "+f"((acc)[0]), "+f"((acc)[1]), "+f"((acc)[2]), "+f"((acc)[3]) \
                 : "r"((a)[0]), "r"((a)[1]), "r"((a)[2]), "r"((a)[3]), \
                   "r"(b0v), "r"(b1v))

__device__ __forceinline__ uint32_t swz(uint32_t off) {
    return off ^ ((off >> 3) & 0x70);
}

__global__ __launch_bounds__(256, 1) void gemm_mma(
    const __nv_bfloat16* __restrict__ Ahi, const __nv_bfloat16* __restrict__ Alo,
    const __nv_bfloat16* __restrict__ Bhi, const __nv_bfloat16* __restrict__ Blo,
    float* __restrict__ C, const float* __restrict__ bias,
    const float* __restrict__ addsrc, int* dcnt, const int* prog)
{
    extern __shared__ char dsm_raw[];
    const int tid = threadIdx.x;
    const int wid = tid >> 5;
    const int lid = tid & 31;
    const int my = blockIdx.y;
    const int tcz = my >> 6;          // t-chunk 0..7
    const int bz  = my & 63;          // batch
    const int m0 = bz * 1024 + tcz * 128;
    const int n0 = blockIdx.x * 128;

    // gate on rec progress (z GEMM only)
    if (prog) {
        if (tid == 0) {
            const int gcl = bz >> 3;
            const int need = tcz * 128 + 127;
            const int* pp = prog + gcl * 8;
            for (int r = 0; r < 8; r++)
                while (ld_acq(pp + r) < need) __nanosleep(256);
        }
        __syncthreads();
    }

    uint32_t sb0 = smem_u32(dsm_raw);
    const uint32_t sbase = (sb0 + 1023u) & ~1023u;

    const int wm = (wid & 3) * 32;
    const int wn = (wid >> 2) * 64;

    float acc[2][8][4];
#pragma unroll
    for (int mt = 0; mt < 2; mt++)
#pragma unroll
        for (int nt = 0; nt < 8; nt++)
#pragma unroll
            for (int j = 0; j < 4; j++) acc[mt][nt][j] = 0.0f;

    const int rid = tid >> 1;
    const int s0 = (tid & 1) * 4;
    const __nv_bfloat16* srcA_hi = Ahi + (size_t)(m0 + rid) * HD;
    const __nv_bfloat16* srcA_lo = Alo + (size_t)(m0 + rid) * HD;
    const __nv_bfloat16* srcB_hi = Bhi + (size_t)(n0 + rid) * HD;
    const __nv_bfloat16* srcB_lo = Blo + (size_t)(n0 + rid) * HD;

    auto stage = [&](int c, int bsel) {
        const int kb = c * 64;
        const uint32_t tb = sbase + (uint32_t)bsel * 65536u;
#pragma unroll
        for (int j = 0; j < 4; j++) {
            const int seg = s0 + j;
            const uint32_t sw = swz((uint32_t)(rid * 128 + seg * 16));
            const size_t so = (size_t)(kb + seg * 8);
            asm volatile("cp.async.cg.shared.global [%0], [%1], 16;"
                         :: "r"(tb + sw), "l"(srcA_hi + so) : "memory");
            asm volatile("cp.async.cg.shared.global [%0], [%1], 16;"
                         :: "r"(tb + 16384u + sw), "l"(srcA_lo + so) : "memory");
            asm volatile("cp.async.cg.shared.global [%0], [%1], 16;"
                         :: "r"(tb + 32768u + sw), "l"(srcB_hi + so) : "memory");
            asm volatile("cp.async.cg.shared.global [%0], [%1], 16;"
                         :: "r"(tb + 49152u + sw), "l"(srcB_lo + so) : "memory");
        }
    };

    const uint32_t a_row_off0 = (uint32_t)(wm + (lid & 15)) * 128u;
    const uint32_t a_k16 = (uint32_t)(lid >> 4) * 16u;
    const uint32_t b_row_off = (uint32_t)(wn + (lid & 7) + ((lid >> 4) << 3)) * 128u;
    const uint32_t b_k16 = (uint32_t)((lid >> 3) & 1) * 16u;

    stage(0, 0);
    asm volatile("cp.async.commit_group;" ::: "memory");
    stage(1, 1);
    asm volatile("cp.async.commit_group;" ::: "memory");

    for (int c = 0; c < 8; c++) {
        asm volatile("cp.async.wait_group 1;" ::: "memory");
        __syncthreads();

        const uint32_t tb = sbase + (uint32_t)(c & 1) * 65536u;
#pragma unroll
        for (int ks = 0; ks < 4; ks++) {
            const uint32_t ka = (uint32_t)(ks * 32) + a_k16;
            const uint32_t kbcol = (uint32_t)(ks * 32) + b_k16;

            uint32_t fah0[4], fah1[4], fal0[4], fal1[4];
            LDM4(fah0, tb + swz(a_row_off0 + ka));
            LDM4(fah1, tb + swz(a_row_off0 + 2048u + ka));
            LDM4(fal0, tb + 16384u + swz(a_row_off0 + ka));
            LDM4(fal1, tb + 16384u + swz(a_row_off0 + 2048u + ka));

            uint32_t bh[4][4], bl[4][4];
#pragma unroll
            for (int nt16 = 0; nt16 < 4; nt16++) {
                const uint32_t bo = swz(b_row_off + (uint32_t)nt16 * 2048u + kbcol);
                LDM4(bh[nt16], tb + 32768u + bo);
                LDM4(bl[nt16], tb + 49152u + bo);
            }

#pragma unroll
            for (int nt16 = 0; nt16 < 4; nt16++) {
                MMA16816(acc[0][2 * nt16],     fah0, bh[nt16][0], bh[nt16][1]);
                MMA16816(acc[0][2 * nt16 + 1], fah0, bh[nt16][2], bh[nt16][3]);
                MMA16816(acc[1][2 * nt16],     fah1, bh[nt16][0], bh[nt16][1]);
                MMA16816(acc[1][2 * nt16 + 1], fah1, bh[nt16][2], bh[nt16][3]);
                MMA16816(acc[0][2 * nt16],     fah0, bl[nt16][0], bl[nt16][1]);
                MMA16816(acc[0][2 * nt16 + 1], fah0, bl[nt16][2], bl[nt16][3]);
                MMA16816(acc[1][2 * nt16],     fah1, bl[nt16][0], bl[nt16][1]);
                MMA16816(acc[1][2 * nt16 + 1], fah1, bl[nt16][2], bl[nt16][3]);
                MMA16816(acc[0][2 * nt16],     fal0, bh[nt16][0], bh[nt16][1]);
                MMA16816(acc[0][2 * nt16 + 1], fal0, bh[nt16][2], bh[nt16][3]);
                MMA16816(acc[1][2 * nt16],     fal1, bh[nt16][0], bh[nt16][1]);
                MMA16816(acc[1][2 * nt16 + 1], fal1, bh[nt16][2], bh[nt16][3]);
            }
        }
        __syncthreads();
        if (c + 2 < 8) stage(c + 2, c & 1);
        asm volatile("cp.async.commit_group;" ::: "memory");
    }

    const int r0 = lid >> 2, cp2 = (lid & 3) * 2;
#pragma unroll
    for (int mt = 0; mt < 2; mt++) {
        const int m = m0 + wm + mt * 16 + r0;
#pragma unroll
        for (int nt = 0; nt < 8; nt++) {
            const int n = n0 + wn + nt * 8 + cp2;
            float bx = 0.0f, by = 0.0f;
            if (bias) { float2 bb = *(const float2*)&bias[n]; bx = bb.x; by = bb.y; }
            float2 v0 = make_float2(acc[mt][nt][0] + bx, acc[mt][nt][1] + by);
            float2 v1 = make_float2(acc[mt][nt][2] + bx, acc[mt][nt][3] + by);
            if (addsrc) {
                float2 a0 = *(const float2*)&addsrc[(size_t)m * HD + n];
                float2 a1 = *(const float2*)&addsrc[(size_t)(m + 8) * HD + n];
                v0.x += a0.x; v0.y += a0.y;
                v1.x += a1.x; v1.y += a1.y;
            }
            *(float2*)&C[(size_t)m * HD + n] = v0;
            *(float2*)&C[(size_t)(m + 8) * HD + n] = v1;
        }
    }

    if (dcnt) {
        __syncthreads();
        if (tid == 0) { __threadfence(); atomicAdd(dcnt + bz * 8 + tcz, 1); }
    }
}

// ---------------------------------------------------------------------------
// Recurrence: R14's proven 2-groups-of-4 structure. Fine-grained drive gate
// (tid<8 spin their own batch's per-chunk counter) and /16-step progress
// publication for the overlapped z GEMM.
// ---------------------------------------------------------------------------
__global__ __launch_bounds__(256, 1) __cluster_dims__(8, 1, 1)
void rnn_rec(const float* __restrict__ h0, const float* __restrict__ drive,
             const float* __restrict__ W, float* __restrict__ hseq,
             __nv_bfloat16* __restrict__ hhi, __nv_bfloat16* __restrict__ hlo,
             int* __restrict__ dcnt, int* __restrict__ prog)
{
    __shared__ __align__(128) float bufA[2][2048];
    __shared__ __align__(128) float bufB[2][2048];
    __shared__ __align__(128) float stgA[2][256];
    __shared__ __align__(128) float stgB[2][256];
    __shared__ float redA[2048];
    __shared__ float redB[2048];
    __shared__ __align__(8) ull mbars[4];

    const int tid = threadIdx.x;
    uint32_t rank;
    asm("mov.u32 %0, %%cluster_ctarank;" : "=r"(rank));
    const int g   = blockIdx.x >> 3;
    const int b0g = g * 8;
    const int c0g = (int)rank * 64;

    const int ks = tid >> 5, cp = tid & 31;
    const int kbeg = ks * 64;

    ull Wp[64];
    {
        const int col0 = c0g + 2 * cp;
#pragma unroll
        for (int c = 0; c < 2; c++) {
            const ull* wr = (const ull*)(W + (size_t)(col0 + c) * HD + kbeg);
#pragma unroll
            for (int kk = 0; kk < 32; kk += 2) {
                ulonglong2 v = *(const ulonglong2*)(wr + kk);
                Wp[c * 32 + kk]     = v.x;
                Wp[c * 32 + kk + 1] = v.y;
            }
        }
    }

    for (int i = tid; i < 2048; i += 256) {
        int r = i >> 8, b = (i >> 6) & 3, c = i & 63;
        bufA[0][i] = h0[(size_t)(b0g + b) * HD + r * 64 + c];
        bufB[0][i] = h0[(size_t)(b0g + 4 + b) * HD + r * 64 + c];
    }
    for (int i = tid; i < 512; i += 256) {
        int b = i >> 6, c = i & 63;
        float v = h0[(size_t)(b0g + b) * HD + (c0g + c)];
        size_t off = (size_t)(b0g + b) * HSEQ_STRIDE + (c0g + c);
        hseq[off] = v;
        __nv_bfloat16 vh = __float2bfloat16(v);
        hhi[off] = vh;
        hlo[off] = __float2bfloat16(v - __bfloat162float(vh));
    }

    const uint32_t bufA_u = smem_u32(bufA);
    const uint32_t bufB_u = smem_u32(bufB);
    const uint32_t stgA_u = smem_u32(stgA);
    const uint32_t stgB_u = smem_u32(stgB);
    const uint32_t mbar_u = smem_u32(mbars);

    if (tid == 0)
#pragma unroll
        for (int i = 0; i < 4; i++) mbar_init(mbar_u + 8u * i, 1);
    __syncthreads();
    asm volatile("barrier.cluster.arrive.aligned;\n\tbarrier.cluster.wait.aligned;" ::: "memory");

    uint32_t dstA[2], dstB[2], mbA[2], mbB[2];
    if (tid < 8) {
#pragma unroll
        for (int pwp = 0; pwp < 2; pwp++) {
            uint32_t dL, mL;
            dL = bufA_u + (uint32_t)pwp * 8192 + rank * 1024;
            asm volatile("mapa.shared::cluster.u32 %0, %1, %2;" : "=r"(dstA[pwp]) : "r"(dL), "r"(tid));
            mL = mbar_u + 8u * pwp;
            asm volatile("mapa.shared::cluster.u32 %0, %1, %2;" : "=r"(mbA[pwp]) : "r"(mL), "r"(tid));
            dL = bufB_u + (uint32_t)pwp * 8192 + rank * 1024;
            asm volatile("mapa.shared::cluster.u32 %0, %1, %2;" : "=r"(dstB[pwp]) : "r"(dL), "r"(tid));
            mL = mbar_u + 16u + 8u * pwp;
            asm volatile("mapa.shared::cluster.u32 %0, %1, %2;" : "=r"(mbB[pwp]) : "r"(mL), "r"(tid));
        }
    }

    const int col_l = tid >> 2, bb = tid & 3;
    const int cg  = c0g + col_l;
    const int cpc = col_l >> 1, cc = col_l & 1;
    const size_t offA = (size_t)(b0g + bb) * HSEQ_STRIDE + cg;
    const size_t offB = offA + 4 * (size_t)HSEQ_STRIDE;
    const float* drvA = drive + offA;
    const float* drvB = drive + offB;
    float* hsA = hseq + offA;
    float* hsB = hseq + offB;
    __nv_bfloat16* hhiA = hhi + offA;  __nv_bfloat16* hloA = hlo + offA;
    __nv_bfloat16* hhiB = hhi + offB;  __nv_bfloat16* hloB = hlo + offB;
    const int stg_idx = bb * 64 + col_l;
    const int hold_idx = (int)rank * 256 + stg_idx;

    int* progP = prog + g * 8 + (int)rank;

    int phA0 = 0, phA1 = 0, phB0 = 0, phB1 = 0;

    for (int t = 1; t < TT; t++) {
        const int pr = (t - 1) & 1, pw = t & 1;

        // fine-grained drive gate (once per 128 steps; tid<8 spin one batch each)
        if (((t - 1) & 127) == 0) {
            if (tid < 8) {
                const int* dc = dcnt + (b0g + tid) * 8 + ((t - 1) >> 7);
                while (ld_acq(dc) < 4) __nanosleep(256);
            }
            __syncthreads();
        }

        if (tid < 8)
            asm volatile("cp.async.bulk.wait_group.read 2;" ::: "memory");

        float xA = drvA[(size_t)(t - 1) * HD];
        float xB = drvB[(size_t)(t - 1) * HD];

        // ================= group A =================
        if (t >= 2) {
            if (pr == 0) { mbar_wait(mbar_u, phA0);     phA0 ^= 1; }
            else         { mbar_wait(mbar_u + 8, phA1); phA1 ^= 1; }
        }
        if (tid == 0 && t < TT - 1) mbar_expect_tx(mbar_u + 8u * pw, 8192);
        {
            const float* bufc = bufA[pr];
            float hold = bufc[hold_idx];

            ull acc[8];
#pragma unroll
            for (int j = 0; j < 8; j++) acc[j] = 0ull;
            const float* hp0 = bufc + ks * 256;
            const float* hp1 = hp0 + 64;
            const float* hp2 = hp0 + 128;
            const float* hp3 = hp0 + 192;
#pragma unroll
            for (int i = 0; i < 16; i++) {
                ulonglong2 h0p = *(const ulonglong2*)(hp0 + 4 * i);
                ulonglong2 h1p = *(const ulonglong2*)(hp1 + 4 * i);
                ulonglong2 h2p = *(const ulonglong2*)(hp2 + 4 * i);
                ulonglong2 h3p = *(const ulonglong2*)(hp3 + 4 * i);
                ull w0 = Wp[2 * i], w1 = Wp[2 * i + 1];
                ull w2 = Wp[32 + 2 * i], w3 = Wp[32 + 2 * i + 1];
                acc[0] = ffma2(w0, h0p.x, acc[0]); acc[0] = ffma2(w1, h0p.y, acc[0]);
                acc[1] = ffma2(w0, h1p.x, acc[1]); acc[1] = ffma2(w1, h1p.y, acc[1]);
                acc[2] = ffma2(w0, h2p.x, acc[2]); acc[2] = ffma2(w1, h2p.y, acc[2]);
                acc[3] = ffma2(w0, h3p.x, acc[3]); acc[3] = ffma2(w1, h3p.y, acc[3]);
                acc[4] = ffma2(w2, h0p.x, acc[4]); acc[4] = ffma2(w3, h0p.y, acc[4]);
                acc[5] = ffma2(w2, h1p.x, acc[5]); acc[5] = ffma2(w3, h1p.y, acc[5]);
                acc[6] = ffma2(w2, h2p.x, acc[6]); acc[6] = ffma2(w3, h2p.y, acc[6]);
                acc[7] = ffma2(w2, h3p.x, acc[7]); acc[7] = ffma2(w3, h3p.y, acc[7]);
            }
            float* rp = redA + (ks * 32 + cp) * 8;
#pragma unroll
            for (int j = 0; j < 8; j++) { float2 s2 = upk2(acc[j]); rp[j] = s2.x + s2.y; }
            __syncthreads();
            float s = 0.0f;
#pragma unroll
            for (int r = 0; r < 8; r++) s += redA[(r * 32 + cpc) * 8 + cc * 4 + bb];
            float hn = 0.9f * hold + 0.1f * tanhf(s + xA);
            hsA[(size_t)t * HD] = hn;
            __nv_bfloat16 hb = __float2bfloat16(hn);
            hhiA[(size_t)t * HD] = hb;
            hloA[(size_t)t * HD] = __float2bfloat16(hn - __bfloat162float(hb));
            stgA[pw][stg_idx] = hn;
            __syncthreads();
        }
        if (tid < 8 && t < TT - 1) {
            asm volatile("fence.proxy.async.shared::cta;" ::: "memory");
            uint32_t src = stgA_u + (uint32_t)pw * 1024;
            asm volatile(
                "cp.async.bulk.shared::cluster.shared::cta.mbarrier::complete_tx::bytes "
                "[%0], [%1], %2, [%3];"
                :: "r"(dstA[pw]), "r"(src), "r"(1024), "r"(mbA[pw]) : "memory");
            asm volatile("cp.async.bulk.commit_group;" ::: "memory");
        }

        // ================= group B =================
        if (t >= 2) {
            if (pr == 0) { mbar_wait(mbar_u + 16, phB0); phB0 ^= 1; }
            else         { mbar_wait(mbar_u + 24, phB1); phB1 ^= 1; }
        }
        if (tid == 0 && t < TT - 1) mbar_expect_tx(mbar_u + 16 + 8u * pw, 8192);
        {
            const float* bufc = bufB[pr];
            float hold = bufc[hold_idx];

            ull acc[8];
#pragma unroll
            for (int j = 0; j < 8; j++) acc[j] = 0ull;
            const float* hp0 = bufc + ks * 256;
            const float* hp1 = hp0 + 64;
            const float* hp2 = hp0 + 128;
            const float* hp3 = hp0 + 192;
#pragma unroll
            for (int i = 0; i < 16; i++) {
                ulonglong2 h0p = *(const ulonglong2*)(hp0 + 4 * i);
                ulonglong2 h1p = *(const ulonglong2*)(hp1 + 4 * i);
                ulonglong2 h2p = *(const ulonglong2*)(hp2 + 4 * i);
                ulonglong2 h3p = *(const ulonglong2*)(hp3 + 4 * i);
                ull w0 = Wp[2 * i], w1 = Wp[2 * i + 1];
                ull w2 = Wp[32 + 2 * i], w3 = Wp[32 + 2 * i + 1];
                acc[0] = ffma2(w0, h0p.x, acc[0]); acc[0] = ffma2(w1, h0p.y, acc[0]);
                acc[1] = ffma2(w0, h1p.x, acc[1]); acc[1] = ffma2(w1, h1p.y, acc[1]);
                acc[2] = ffma2(w0, h2p.x, acc[2]); acc[2] = ffma2(w1, h2p.y, acc[2]);
                acc[3] = ffma2(w0, h3p.x, acc[3]); acc[3] = ffma2(w1, h3p.y, acc[3]);
                acc[4] = ffma2(w2, h0p.x, acc[4]); acc[4] = ffma2(w3, h0p.y, acc[4]);
                acc[5] = ffma2(w2, h1p.x, acc[5]); acc[5] = ffma2(w3, h1p.y, acc[5]);
                acc[6] = ffma2(w2, h2p.x, acc[6]); acc[6] = ffma2(w3, h2p.y, acc[6]);
                acc[7] = ffma2(w2, h3p.x, acc[7]); acc[7] = ffma2(w3, h3p.y, acc[7]);
            }
            float* rp = redB + (ks * 32 + cp) * 8;
#pragma unroll
            for (int j = 0; j < 8; j++) { float2 s2 = upk2(acc[j]); rp[j] = s2.x + s2.y; }
            __syncthreads();
            float s = 0.0f;
#pragma unroll
            for (int r = 0; r < 8; r++) s += redB[(r * 32 + cpc) * 8 + cc * 4 + bb];
            float hn = 0.9f * hold + 0.1f * tanhf(s + xB);
            hsB[(size_t)t * HD] = hn;
            __nv_bfloat16 hb = __float2bfloat16(hn);
            hhiB[(size_t)t * HD] = hb;
            hloB[(size_t)t * HD] = __float2bfloat16(hn - __bfloat162float(hb));
            stgB[pw][stg_idx] = hn;
            __syncthreads();
        }
        if (tid < 8 && t < TT - 1) {
            asm volatile("fence.proxy.async.shared::cta;" ::: "memory");
            uint32_t src = stgB_u + (uint32_t)pw * 1024;
            asm volatile(
                "cp.async.bulk.shared::cluster.shared::cta.mbarrier::complete_tx::bytes "
                "[%0], [%1], %2, [%3];"
                :: "r"(dstB[pw]), "r"(src), "r"(1024), "r"(mbB[pw]) : "memory");
            asm volatile("cp.async.bulk.commit_group;" ::: "memory");
        }

        // publish progress every 16 steps (single gpu fence; covers A and B)
        if ((t & 15) == 15 && tid == 0) {
            __threadfence();
            asm volatile("st.release.gpu.u32 [%0], %1;" :: "l"(progP), "r"(t) : "memory");
        }
    }

    if (tid < 8) asm volatile("cp.async.bulk.wait_group.read 0;" ::: "memory");
    asm volatile("barrier.cluster.arrive.aligned;\n\tbarrier.cluster.wait.aligned;" ::: "memory");
}

// ---------------------------------------------------------------------------
extern "C" void kernel_launch(void* const* d_in, const int* in_sizes, int n_in,
                              void* d_out, int out_size)
{
    const float* h0 = (const float*)d_in[0];
    const float* s  = (const float*)d_in[1];
    const float* u  = (const float*)d_in[2];
    const float* W  = (const float*)d_in[3];
    const float* b  = (const float*)d_in[4];
    const float* Bs = (const float*)d_in[5];
    // d_in[6] = Bu (identity by construction)
    const float* Wz = (const float*)d_in[7];
    const float* bz = (const float*)d_in[8];

    float* hseq = (float*)d_out;                         // [B,T,H]
    float* zseq = (float*)d_out + (size_t)BB * TT * HD;  // [B,T,Z]
    float* drive = zseq;  // scratch; overwritten progressively by z GEMM (gated)

    void *pAhi, *pAlo, *pChi, *pClo, *pBhi, *pBlo, *pB2hi, *pB2lo, *pDc, *pPg;
    cudaGetSymbolAddress(&pAhi, g_Ahi);
    cudaGetSymbolAddress(&pAlo, g_Alo);
    cudaGetSymbolAddress(&pChi, g_Chi);
    cudaGetSymbolAddress(&pClo, g_Clo);
    cudaGetSymbolAddress(&pBhi, g_Bhi);
    cudaGetSymbolAddress(&pBlo, g_Blo);
    cudaGetSymbolAddress(&pB2hi, g_B2hi);
    cudaGetSymbolAddress(&pB2lo, g_B2lo);
    cudaGetSymbolAddress(&pDc, g_dcnt);
    cudaGetSymbolAddress(&pPg, g_prog);

    const int GEMM_SMEM = 2 * 65536 + 1024;
    cudaFuncSetAttribute(gemm_mma, cudaFuncAttributeMaxDynamicSharedMemorySize, GEMM_SMEM);

    // streams/events created ONCE on the first (non-captured) call; reused.
    static cudaStream_t s1 = nullptr, s2 = nullptr;
    static cudaEvent_t ev0 = nullptr, evF = nullptr, ev1 = nullptr, ev2 = nullptr;
    if (!s1) {
        cudaStreamCreateWithFlags(&s1, cudaStreamNonBlocking);
        cudaStreamCreateWithFlags(&s2, cudaStreamNonBlocking);
        cudaEventCreateWithFlags(&ev0, cudaEventDisableTiming);
        cudaEventCreateWithFlags(&evF, cudaEventDisableTiming);
        cudaEventCreateWithFlags(&ev1, cudaEventDisableTiming);
        cudaEventCreateWithFlags(&ev2, cudaEventDisableTiming);
    }

    dim3 blk(256);
    dim3 grd(4, 512);

    // --- prologue on capture stream ---
    init_sync<<<1, 256>>>();
    cudaEventRecord(ev0, 0);                 // rec only needs zeroed sync vars
    cvt_split<<<2048, 256>>>((const float4*)s, (ull*)pAhi, (ull*)pAlo, 8388608);
    cvt_split<<<256, 256>>>((const float4*)Bs, (ull*)pBhi, (ull*)pBlo, 65536);
    cvt_split<<<256, 256>>>((const float4*)Wz, (ull*)pB2hi, (ull*)pB2lo, 65536);
    cudaEventRecord(evF, 0);

    // --- branch 1: recurrence (starts early; gated on drive progress) ---
    cudaStreamWaitEvent(s1, ev0, 0);
    rnn_rec<<<64, 256, 0, s1>>>(h0, drive, W, hseq,
                                (__nv_bfloat16*)pChi, (__nv_bfloat16*)pClo,
                                (int*)pDc, (int*)pPg);
    cudaEventRecord(ev1, s1);

    // --- branch 2: drive GEMM (producer) then z GEMM (gated on rec) ---
    cudaStreamWaitEvent(s2, evF, 0);
    gemm_mma<<<grd, blk, GEMM_SMEM, s2>>>(
        (const __nv_bfloat16*)pAhi, (const __nv_bfloat16*)pAlo,
        (const __nv_bfloat16*)pBhi, (const __nv_bfloat16*)pBlo,
        drive, b, u, (int*)pDc, nullptr);
    gemm_mma<<<grd, blk, GEMM_SMEM, s2>>>(
        (const __nv_bfloat16*)pChi, (const __nv_bfloat16*)pClo,
        (const __nv_bfloat16*)pB2hi, (const __nv_bfloat16*)pB2lo,
        zseq, bz, nullptr, nullptr, (const int*)pPg);
    cudaEventRecord(ev2, s2);

    // --- join ---
    cudaStreamWaitEvent(0, ev1, 0);
    cudaStreamWaitEvent(0, ev2, 0);
}